// round 5
// baseline (speedup 1.0000x reference)
#include <cuda_runtime.h>
#include <stdint.h>

// Problem constants
#define BATCH 8
#define H 2048
#define W 2048
#define HW (H * W)
#define TOPK 8192
#define MAXP 400000      // per-batch peak capacity (expected ~167k)
#define NBINS 8192       // value histogram bins (mantissa bits [22:10] for v in [0.5,1))
#define CAPB 4096        // threshold-bin candidate capacity (expected ~250)
#define PCAP 512         // per-block smem peak buffer (expected ~164/block)

// ---------------- device scratch ----------------
__device__ unsigned long long d_peaks[BATCH][MAXP];   // key = (~float_bits)<<32 | idx
__device__ int                d_pcount[BATCH];
__device__ unsigned int       d_hist[BATCH][NBINS];
__device__ unsigned int       d_binoff[BATCH][NBINS]; // exclusive prefix of hist
__device__ int                d_thrbin[BATCH];
__device__ int                d_cA[BATCH];            // #elements strictly above threshold bin
__device__ int                d_cB[BATCH];            // #elements in threshold bin (capped)
__device__ int                d_cBcnt[BATCH];         // scatter counter for B
__device__ unsigned long long d_bufA[BATCH][TOPK];
__device__ unsigned long long d_bufB[BATCH][CAPB];

// value -> bin, monotone: larger value => smaller bin
__device__ __forceinline__ unsigned value_bin(unsigned bits) {
    if (bits >= 0x3F800000u) return 0u;          // v >= 1.0 (shouldn't happen)
    if (bits <  0x3F000000u) return NBINS - 1u;  // v < 0.5: irrelevant, worst bin
    return (NBINS - 1u) - ((bits - 0x3F000000u) >> 10);
}

// ---------------- init (split into 3 so nms is the 4th launch -> ncu captures it) ----------------
__global__ void init_a() {   // zero first half of hist
    int g = blockIdx.x * blockDim.x + threadIdx.x;
    for (int i = g; i < BATCH * NBINS / 2; i += gridDim.x * blockDim.x)
        ((unsigned int*)d_hist)[i] = 0u;
}
__global__ void init_b() {   // zero second half of hist
    int g = blockIdx.x * blockDim.x + threadIdx.x;
    for (int i = g; i < BATCH * NBINS / 2; i += gridDim.x * blockDim.x)
        ((unsigned int*)d_hist)[BATCH * NBINS / 2 + i] = 0u;
}
__global__ void init_c() {   // counters
    int t = threadIdx.x;
    if (t < BATCH) {
        d_pcount[t] = 0;
        d_cA[t] = 0;
        d_cB[t] = 0;
        d_cBcnt[t] = 0;
        d_thrbin[t] = NBINS - 1;
    }
}

// ---------------- NMS: 5x5 local max + fused histogram, block-aggregated append ----------------
#define TX 128
#define TY 32
#define NTHR 512

__global__ __launch_bounds__(NTHR) void nms_kernel(const float* __restrict__ s) {
    __shared__ float tile[TY + 4][TX + 4];   // 36 x 132
    __shared__ float hmax[TY + 4][TX];       // 36 x 128
    __shared__ unsigned long long pbuf[PCAP];
    __shared__ int pcnt;
    __shared__ int pbase;

    int b  = blockIdx.z;
    int x0 = blockIdx.x * TX;
    int y0 = blockIdx.y * TY;
    const float* img = s + (size_t)b * HW;
    int tid = threadIdx.x;

    if (tid == 0) pcnt = 0;

    // Load tile + halo (clamped; clamped values only influence discarded border outputs)
    for (int i = tid; i < (TY + 4) * (TX + 4); i += NTHR) {
        int r = i / (TX + 4), c = i % (TX + 4);
        int gy = min(max(y0 + r - 2, 0), H - 1);
        int gx = min(max(x0 + c - 2, 0), W - 1);
        tile[r][c] = img[gy * W + gx];
    }
    __syncthreads();

    // Horizontal 5-max
    for (int i = tid; i < (TY + 4) * TX; i += NTHR) {
        int r = i / TX, c = i % TX;
        float m = tile[r][c];
        m = fmaxf(m, tile[r][c + 1]);
        m = fmaxf(m, tile[r][c + 2]);
        m = fmaxf(m, tile[r][c + 3]);
        m = fmaxf(m, tile[r][c + 4]);
        hmax[r][c] = m;
    }
    __syncthreads();

    // Vertical 5-max + peak test; append to smem buffer
    int c  = tid & 127;
    int r0 = tid >> 7;  // 0..3
    for (int rr = r0; rr < TY; rr += 4) {
        float v = tile[rr + 2][c + 2];
        float m = hmax[rr][c];
        m = fmaxf(m, hmax[rr + 1][c]);
        m = fmaxf(m, hmax[rr + 2][c]);
        m = fmaxf(m, hmax[rr + 3][c]);
        m = fmaxf(m, hmax[rr + 4][c]);
        int gx = x0 + c, gy = y0 + rr;
        bool peak = (v >= m) && (gx >= 2) && (gx < W - 2) && (gy >= 2) && (gy < H - 2);
        if (peak) {
            unsigned bits = __float_as_uint(v);
            unsigned idx  = (unsigned)(gy * W + gx);
            unsigned long long key = ((unsigned long long)(~bits) << 32) | idx;
            atomicAdd(&d_hist[b][value_bin(bits)], 1u);   // REDG, spread addresses
            int pos = atomicAdd(&pcnt, 1);
            if (pos < PCAP) {
                pbuf[pos] = key;
            } else {  // overflow (pathological only): direct global append
                int g = atomicAdd(&d_pcount[b], 1);
                if (g < MAXP) d_peaks[b][g] = key;
            }
        }
    }
    __syncthreads();

    int n = min(pcnt, PCAP);
    if (tid == 0) pbase = atomicAdd(&d_pcount[b], n);   // ONE global atomic per block
    __syncthreads();
    for (int i = tid; i < n; i += NTHR)
        d_peaks[b][pbase + i] = pbuf[i];
}

// ---------------- threshold bin + full exclusive bin-offset scan (one block per batch) ----------------
__global__ void threshold_kernel() {
    __shared__ unsigned ssum[256];
    int b = blockIdx.x;
    int t = threadIdx.x;  // 256, each owns 32 consecutive bins
    const int CH = NBINS / 256;  // 32

    unsigned local[CH];
    unsigned sum = 0;
#pragma unroll
    for (int j = 0; j < CH; j++) {
        local[j] = sum;                       // exclusive within chunk
        sum += d_hist[b][t * CH + j];
    }
    ssum[t] = sum;
    __syncthreads();

    // inclusive Hillis-Steele scan of chunk sums
    for (int off = 1; off < 256; off <<= 1) {
        unsigned x = (t >= off) ? ssum[t - off] : 0u;
        __syncthreads();
        ssum[t] += x;
        __syncthreads();
    }
    unsigned incl = ssum[t];
    unsigned excl = incl - sum;

#pragma unroll
    for (int j = 0; j < CH; j++)
        d_binoff[b][t * CH + j] = excl + local[j];

    if (excl < TOPK && incl >= TOPK) {  // threshold bin is inside this chunk
        unsigned cum = excl;
        for (int j = 0; j < CH; j++) {
            unsigned cc = d_hist[b][t * CH + j];
            if (cum + cc >= TOPK) {
                d_thrbin[b] = t * CH + j;
                d_cA[b] = (int)cum;
                d_cB[b] = (int)min(cc, (unsigned)CAPB);
                break;
            }
            cum += cc;
        }
    }
}

// ---------------- scatter: counting-sort A by bin; threshold bin -> B ----------------
__global__ void scatter_kernel() {
    int b = blockIdx.y;
    int n = min(d_pcount[b], MAXP);
    unsigned thr = (unsigned)d_thrbin[b];
    for (int i = blockIdx.x * blockDim.x + threadIdx.x; i < n; i += gridDim.x * blockDim.x) {
        unsigned long long key = d_peaks[b][i];
        unsigned bits = ~(unsigned)(key >> 32);
        unsigned bin = value_bin(bits);
        if (bin < thr) {
            unsigned old = atomicAdd(&d_hist[b][bin], (unsigned)-1);  // consume hist as rank
            unsigned pos = d_binoff[b][bin] + old - 1u;               // < cA <= TOPK by construction
            d_bufA[b][pos] = key;
        } else if (bin == thr) {
            int pos = atomicAdd(&d_cBcnt[b], 1);
            if (pos < CAPB) d_bufB[b][pos] = key;
        }
    }
}

// ---------------- sort: tiny per-bin sorts for A, bitonic for B ----------------
__global__ void sort_kernel() {
    __shared__ unsigned long long sb[CAPB];  // 32 KB
    int b = blockIdx.y;

    if (blockIdx.x < NBINS / 256) {
        // Role A: one thread per bin, in-place selection sort of its segment
        int bin = blockIdx.x * 256 + threadIdx.x;
        int thr = d_thrbin[b];
        if (bin < thr) {
            int start = (int)d_binoff[b][bin];
            int end   = (bin + 1 < NBINS) ? (int)d_binoff[b][bin + 1] : d_cA[b];
            for (int i = start; i < end - 1; i++) {
                unsigned long long mv = d_bufA[b][i];
                int mi = i;
                for (int j = i + 1; j < end; j++) {
                    unsigned long long vj = d_bufA[b][j];
                    if (vj < mv) { mv = vj; mi = j; }
                }
                if (mi != i) { d_bufA[b][mi] = d_bufA[b][i]; d_bufA[b][i] = mv; }
            }
        }
    } else {
        // Role B: bitonic sort of the threshold bin (ascending key = value desc, idx asc)
        int cnt = min(d_cBcnt[b], CAPB);
        int N = 256;
        while (N < cnt) N <<= 1;  // <= CAPB
        for (int i = threadIdx.x; i < N; i += blockDim.x)
            sb[i] = (i < cnt) ? d_bufB[b][i] : 0xFFFFFFFFFFFFFFFFull;
        __syncthreads();
        for (int k = 2; k <= N; k <<= 1) {
            for (int j = k >> 1; j > 0; j >>= 1) {
                for (int i = threadIdx.x; i < N; i += blockDim.x) {
                    int ixj = i ^ j;
                    if (ixj > i) {
                        unsigned long long a = sb[i];
                        unsigned long long cc = sb[ixj];
                        bool up = ((i & k) == 0);
                        if ((a > cc) == up) { sb[i] = cc; sb[ixj] = a; }
                    }
                }
                __syncthreads();
            }
        }
        for (int i = threadIdx.x; i < cnt; i += blockDim.x)
            d_bufB[b][i] = sb[i];
    }
}

// ---------------- per-keypoint soft-argmax / dispersity / bilinear rescore ----------------
__global__ void final_kernel(const float* __restrict__ s, float* __restrict__ out) {
    int g = blockIdx.x * blockDim.x + threadIdx.x;
    if (g >= BATCH * TOPK) return;
    int b = g / TOPK, k = g % TOPK;

    int cA = min(d_cA[b], TOPK);
    int cB = min(d_cB[b], CAPB);
    unsigned long long key;
    if (k < cA) key = d_bufA[b][k];
    else        key = d_bufB[b][min(k - cA, cB - 1)];
    unsigned idx = (unsigned)key;
    int ky = (int)(idx >> 11);   // W = 2048
    int kx = (int)(idx & 2047u);
    const float* img = s + (size_t)b * HW;

    // 5x5 patch (keypoints are >= 2 px from every border -> fully in bounds)
    float p[25];
    float mx = -1e30f;
#pragma unroll
    for (int di = 0; di < 5; di++)
#pragma unroll
        for (int dj = 0; dj < 5; dj++) {
            float v = img[(ky + di - 2) * W + (kx + dj - 2)];
            p[di * 5 + dj] = v;
            mx = fmaxf(mx, v);
        }

    float e[25];
    float se = 0.f, sx = 0.f, sy = 0.f;
#pragma unroll
    for (int i = 0; i < 25; i++) {
        float dx = (float)(i % 5) - 2.0f;
        float dy = (float)(i / 5) - 2.0f;
        float ev = __expf((p[i] - mx) * 10.0f);  // 1 / TEMPERATURE
        e[i] = ev;
        se += ev; sx += ev * dx; sy += ev * dy;
    }
    float xres = sx / se;
    float yres = sy / se;

    float dsum = 0.f;
#pragma unroll
    for (int i = 0; i < 25; i++) {
        float dx = ((float)(i % 5) - 2.0f - xres) * 0.5f;  // / RADIUS
        float dy = ((float)(i / 5) - 2.0f - yres) * 0.5f;
        dsum += e[i] * (dx * dx + dy * dy);
    }
    float disp = dsum / se;

    float kxy_x = ((float)kx + xres) / 2047.0f * 2.0f - 1.0f;
    float kxy_y = ((float)ky + yres) / 2047.0f * 2.0f - 1.0f;

    // bilinear resample (align_corners=True), matching reference clamp semantics
    float px = (kxy_x + 1.0f) * 0.5f * 2047.0f;
    float py = (kxy_y + 1.0f) * 0.5f * 2047.0f;
    int x0 = min(max((int)floorf(px), 0), W - 1);
    int y0 = min(max((int)floorf(py), 0), H - 1);
    int x1 = min(x0 + 1, W - 1);
    int y1 = min(y0 + 1, H - 1);
    float wx = px - (float)x0;
    float wy = py - (float)y0;
    float v00 = img[y0 * W + x0], v01 = img[y0 * W + x1];
    float v10 = img[y1 * W + x0], v11 = img[y1 * W + x1];
    float ks = v00 * (1.f - wx) * (1.f - wy) + v01 * wx * (1.f - wy)
             + v10 * (1.f - wx) * wy + v11 * wx * wy;

    // output layout: kxy (B,K,2) | kscore (B,K) | disp (B,K)
    out[(size_t)(b * TOPK + k) * 2 + 0] = kxy_x;
    out[(size_t)(b * TOPK + k) * 2 + 1] = kxy_y;
    out[(size_t)BATCH * TOPK * 2 + b * TOPK + k] = ks;
    out[(size_t)BATCH * TOPK * 3 + b * TOPK + k] = disp;
}

// ---------------- launch ----------------
extern "C" void kernel_launch(void* const* d_in, const int* in_sizes, int n_in,
                              void* d_out, int out_size) {
    const float* s = (const float*)d_in[0];
    float* out = (float*)d_out;

    init_a<<<128, 256>>>();
    init_b<<<128, 256>>>();
    init_c<<<1, 32>>>();
    nms_kernel<<<dim3(W / TX, H / TY, BATCH), NTHR>>>(s);       // 4th launch -> ncu capture
    threshold_kernel<<<BATCH, 256>>>();
    scatter_kernel<<<dim3(96, BATCH), 256>>>();
    sort_kernel<<<dim3(NBINS / 256 + 1, BATCH), 256>>>();
    final_kernel<<<(BATCH * TOPK + 255) / 256, 256>>>(s, out);
}

// round 6
// speedup vs baseline: 11.8710x; 11.8710x over previous
#include <cuda_runtime.h>
#include <stdint.h>

// Problem constants
#define BATCH 8
#define H 2048
#define W 2048
#define HW (H * W)
#define TOPK 8192
#define MAXP 400000      // per-batch peak capacity (expected ~167k)
#define NBINS 65536      // value histogram bins (mantissa bits [22:7] for v in [0.5,1))
#define CAPB 4096        // threshold-bin candidate capacity (expected ~20)
#define PCAP 512         // per-block smem peak buffer (expected ~164/block)

// ---------------- device scratch ----------------
__device__ unsigned long long d_peaks[BATCH][MAXP];   // key = (~float_bits)<<32 | idx
__device__ int                d_pcount[BATCH];
__device__ unsigned int       d_hist[BATCH][NBINS];
__device__ unsigned int       d_binoff[BATCH][NBINS]; // exclusive prefix of hist
__device__ int                d_thrbin[BATCH];
__device__ int                d_cA[BATCH];            // #elements strictly above threshold bin
__device__ int                d_cB[BATCH];            // #elements in threshold bin (capped)
__device__ int                d_cBcnt[BATCH];         // scatter counter for B
__device__ unsigned long long d_bufA[BATCH][TOPK];
__device__ unsigned long long d_bufB[BATCH][CAPB];

// value -> bin, monotone: larger value => smaller bin
__device__ __forceinline__ unsigned value_bin(unsigned bits) {
    if (bits >= 0x3F800000u) return 0u;          // v >= 1.0 (shouldn't happen)
    if (bits <  0x3F000000u) return NBINS - 1u;  // v < 0.5: irrelevant, worst bin
    return (NBINS - 1u) - ((bits - 0x3F000000u) >> 7);
}

// ---------------- init (3 launches so nms is the 4th -> ncu captures it) ----------------
__global__ void init_a() {   // zero first half of hist (vectorized)
    int g = blockIdx.x * blockDim.x + threadIdx.x;
    uint4* p = (uint4*)d_hist;
    for (int i = g; i < BATCH * NBINS / 8; i += gridDim.x * blockDim.x)
        p[i] = make_uint4(0, 0, 0, 0);
}
__global__ void init_b() {   // zero second half of hist
    int g = blockIdx.x * blockDim.x + threadIdx.x;
    uint4* p = (uint4*)d_hist + BATCH * NBINS / 8;
    for (int i = g; i < BATCH * NBINS / 8; i += gridDim.x * blockDim.x)
        p[i] = make_uint4(0, 0, 0, 0);
}
__global__ void init_c() {   // counters
    int t = threadIdx.x;
    if (t < BATCH) {
        d_pcount[t] = 0;
        d_cA[t] = 0;
        d_cB[t] = 0;
        d_cBcnt[t] = 0;
        d_thrbin[t] = NBINS - 1;
    }
}

// ---------------- NMS: 5x5 local max + fused histogram, block-aggregated append ----------------
#define TX 128
#define TY 32
#define NTHR 512

__global__ __launch_bounds__(NTHR) void nms_kernel(const float* __restrict__ s) {
    __shared__ float tile[TY + 4][TX + 4];   // 36 x 132
    __shared__ float hmax[TY + 4][TX];       // 36 x 128
    __shared__ unsigned long long pbuf[PCAP];
    __shared__ int pcnt;
    __shared__ int pbase;

    int b  = blockIdx.z;
    int x0 = blockIdx.x * TX;
    int y0 = blockIdx.y * TY;
    const float* img = s + (size_t)b * HW;
    int tid = threadIdx.x;
    int c   = tid & 127;
    int r0  = tid >> 7;  // 0..3

    if (tid == 0) pcnt = 0;

    // Main tile region: coalesced, no div/mod. tile col = c+2 <-> global x0+c.
#pragma unroll
    for (int r = r0; r < TY + 4; r += 4) {
        int gy = min(max(y0 + r - 2, 0), H - 1);
        tile[r][c + 2] = img[gy * W + (x0 + c)];   // x0+c in [0, W) for all blocks? x0+c <= W-1 yes
    }
    // Halo columns: tile cols 0,1,130,131 (4 per row, 36 rows = 144 loads)
    for (int i = tid; i < (TY + 4) * 4; i += NTHR) {
        int r = i >> 2, hh = i & 3;
        int tc = (hh < 2) ? hh : 128 + hh;       // 0,1,130,131
        int gx = min(max(x0 + tc - 2, 0), W - 1);
        int gy = min(max(y0 + r - 2, 0), H - 1);
        tile[r][tc] = img[gy * W + gx];
    }
    __syncthreads();

    // Horizontal 5-max: rows 0..35, cols 0..127 (tile cols c..c+4)
#pragma unroll
    for (int r = r0; r < TY + 4; r += 4) {
        float m = tile[r][c];
        m = fmaxf(m, tile[r][c + 1]);
        m = fmaxf(m, tile[r][c + 2]);
        m = fmaxf(m, tile[r][c + 3]);
        m = fmaxf(m, tile[r][c + 4]);
        hmax[r][c] = m;
    }
    __syncthreads();

    // Vertical 5-max + peak test; append to smem buffer
    for (int rr = r0; rr < TY; rr += 4) {
        float v = tile[rr + 2][c + 2];
        float m = hmax[rr][c];
        m = fmaxf(m, hmax[rr + 1][c]);
        m = fmaxf(m, hmax[rr + 2][c]);
        m = fmaxf(m, hmax[rr + 3][c]);
        m = fmaxf(m, hmax[rr + 4][c]);
        int gx = x0 + c, gy = y0 + rr;
        bool peak = (v >= m) && (gx >= 2) && (gx < W - 2) && (gy >= 2) && (gy < H - 2);
        if (peak) {
            unsigned bits = __float_as_uint(v);
            unsigned idx  = (unsigned)(gy * W + gx);
            unsigned long long key = ((unsigned long long)(~bits) << 32) | idx;
            atomicAdd(&d_hist[b][value_bin(bits)], 1u);   // REDG, well-spread addresses
            int pos = atomicAdd(&pcnt, 1);
            if (pos < PCAP) {
                pbuf[pos] = key;
            } else {  // overflow (pathological only): direct global append
                int g = atomicAdd(&d_pcount[b], 1);
                if (g < MAXP) d_peaks[b][g] = key;
            }
        }
    }
    __syncthreads();

    int n = min(pcnt, PCAP);
    if (tid == 0) pbase = atomicAdd(&d_pcount[b], n);   // ONE global atomic per block
    __syncthreads();
    for (int i = tid; i < n; i += NTHR)
        d_peaks[b][pbase + i] = pbuf[i];
}

// ---------------- threshold bin + exclusive bin-offset scan (one block per batch) ----------------
__global__ __launch_bounds__(1024) void threshold_kernel() {
    __shared__ unsigned ssum[1024];
    int b = blockIdx.x;
    int t = threadIdx.x;                 // 1024 threads, each owns 64 consecutive bins
    const int CH = NBINS / 1024;         // 64

    unsigned local[CH];
    unsigned sum = 0;
#pragma unroll
    for (int j = 0; j < CH; j++) {
        local[j] = sum;                  // exclusive within chunk
        sum += d_hist[b][t * CH + j];
    }
    ssum[t] = sum;
    __syncthreads();

    // inclusive Hillis-Steele scan of chunk sums
    for (int off = 1; off < 1024; off <<= 1) {
        unsigned x = (t >= off) ? ssum[t - off] : 0u;
        __syncthreads();
        ssum[t] += x;
        __syncthreads();
    }
    unsigned incl = ssum[t];
    unsigned excl = incl - sum;

#pragma unroll
    for (int j = 0; j < CH; j++)
        d_binoff[b][t * CH + j] = excl + local[j];

    if (excl < TOPK && incl >= TOPK) {   // threshold bin is inside this chunk
        unsigned cum = excl;
        for (int j = 0; j < CH; j++) {
            unsigned cc = d_hist[b][t * CH + j];
            if (cum + cc >= TOPK) {
                d_thrbin[b] = t * CH + j;
                d_cA[b] = (int)cum;
                d_cB[b] = (int)min(cc, (unsigned)CAPB);
                break;
            }
            cum += cc;
        }
    }
}

// ---------------- scatter: counting-sort A by bin; threshold bin -> B ----------------
__global__ void scatter_kernel() {
    int b = blockIdx.y;
    int n = min(d_pcount[b], MAXP);
    unsigned thr = (unsigned)d_thrbin[b];
    for (int i = blockIdx.x * blockDim.x + threadIdx.x; i < n; i += gridDim.x * blockDim.x) {
        unsigned long long key = d_peaks[b][i];
        unsigned bits = ~(unsigned)(key >> 32);
        unsigned bin = value_bin(bits);
        if (bin < thr) {
            unsigned old = atomicAdd(&d_hist[b][bin], (unsigned)-1);  // consume hist as rank
            unsigned pos = d_binoff[b][bin] + old - 1u;               // stays inside segment
            d_bufA[b][pos] = key;
        } else if (bin == thr) {
            int pos = atomicAdd(&d_cBcnt[b], 1);
            if (pos < CAPB) d_bufB[b][pos] = key;
        }
    }
}

// ---------------- sortA: warp-cooperative rank sort per bin ----------------
#define SA_BLOCKS 64
#define SA_WPB 8    // warps per block

__global__ __launch_bounds__(SA_WPB * 32) void sortA_kernel() {
    __shared__ unsigned long long stage[SA_WPB][256];  // 16 KB: per-warp staging
    int b     = blockIdx.y;
    int wslot = threadIdx.x >> 5;
    int lane  = threadIdx.x & 31;
    int warp  = blockIdx.x * SA_WPB + wslot;
    int nwarp = SA_BLOCKS * SA_WPB;
    int thr   = d_thrbin[b];

    // each warp scans groups of 32 bins; lanes probe boundaries in parallel
    for (int bin0 = warp * 32; bin0 < thr; bin0 += nwarp * 32) {
        int mybin = bin0 + lane;
        int st = 0, en = 0;
        if (mybin < thr) {
            st = (int)d_binoff[b][mybin];
            en = (int)d_binoff[b][mybin + 1];   // mybin+1 <= thr <= NBINS-1
        }
        unsigned need = __ballot_sync(0xffffffffu, (en - st) >= 2);
        while (need) {
            int src = __ffs(need) - 1;
            need &= need - 1;
            int start = __shfl_sync(0xffffffffu, st, src);
            int n     = __shfl_sync(0xffffffffu, en, src) - start;

            if (n <= 32) {
                // register-only rank sort via shuffles
                unsigned long long e = (lane < n) ? d_bufA[b][start + lane]
                                                  : 0xFFFFFFFFFFFFFFFFull;
                int rank = 0;
                for (int j = 0; j < n; j++) {
                    unsigned long long f = __shfl_sync(0xffffffffu, e, j);
                    rank += (f < e);
                }
                __syncwarp();
                if (lane < n) d_bufA[b][start + rank] = e;
            } else if (n <= 256) {
                // smem-staged rank sort
                for (int i = lane; i < n; i += 32) stage[wslot][i] = d_bufA[b][start + i];
                __syncwarp();
                for (int i = lane; i < n; i += 32) {
                    unsigned long long e = stage[wslot][i];
                    int rank = 0;
                    for (int j = 0; j < n; j++) rank += (stage[wslot][j] < e);
                    d_bufA[b][start + rank] = e;
                }
                __syncwarp();
            } else {
                // register-buffered fallback (n <= 1024)
                unsigned long long ebuf[32];
                int rbuf[32];
                int cnt = 0;
                for (int i = lane; i < n && cnt < 32; i += 32, cnt++) {
                    unsigned long long e = d_bufA[b][start + i];
                    int rank = 0;
                    for (int j = 0; j < n; j++) rank += (d_bufA[b][start + j] < e);
                    ebuf[cnt] = e; rbuf[cnt] = rank;
                }
                __syncwarp();
                for (int q = 0; q < cnt; q++) d_bufA[b][start + rbuf[q]] = ebuf[q];
                __syncwarp();
            }
        }
    }
}

// ---------------- sortB: block rank sort of threshold bin ----------------
__global__ __launch_bounds__(256) void sortB_kernel() {
    __shared__ unsigned long long sb[CAPB];  // 32 KB
    int b = blockIdx.x;
    int cnt = min(d_cBcnt[b], CAPB);
    for (int i = threadIdx.x; i < cnt; i += 256) sb[i] = d_bufB[b][i];
    __syncthreads();
    for (int i = threadIdx.x; i < cnt; i += 256) {
        unsigned long long e = sb[i];
        int rank = 0;
        for (int j = 0; j < cnt; j++) rank += (sb[j] < e);
        d_bufB[b][rank] = e;
    }
}

// ---------------- per-keypoint soft-argmax / dispersity / bilinear rescore ----------------
__global__ void final_kernel(const float* __restrict__ s, float* __restrict__ out) {
    int g = blockIdx.x * blockDim.x + threadIdx.x;
    if (g >= BATCH * TOPK) return;
    int b = g / TOPK, k = g % TOPK;

    int cA = min(d_cA[b], TOPK);
    int cB = min(d_cB[b], CAPB);
    unsigned long long key;
    if (k < cA) key = d_bufA[b][k];
    else        key = d_bufB[b][min(k - cA, cB - 1)];
    unsigned idx = (unsigned)key;
    int ky = (int)(idx >> 11);   // W = 2048
    int kx = (int)(idx & 2047u);
    const float* img = s + (size_t)b * HW;

    // 5x5 patch (keypoints are >= 2 px from every border -> fully in bounds)
    float p[25];
    float mx = -1e30f;
#pragma unroll
    for (int di = 0; di < 5; di++)
#pragma unroll
        for (int dj = 0; dj < 5; dj++) {
            float v = img[(ky + di - 2) * W + (kx + dj - 2)];
            p[di * 5 + dj] = v;
            mx = fmaxf(mx, v);
        }

    float e[25];
    float se = 0.f, sx = 0.f, sy = 0.f;
#pragma unroll
    for (int i = 0; i < 25; i++) {
        float dx = (float)(i % 5) - 2.0f;
        float dy = (float)(i / 5) - 2.0f;
        float ev = __expf((p[i] - mx) * 10.0f);  // 1 / TEMPERATURE
        e[i] = ev;
        se += ev; sx += ev * dx; sy += ev * dy;
    }
    float xres = sx / se;
    float yres = sy / se;

    float dsum = 0.f;
#pragma unroll
    for (int i = 0; i < 25; i++) {
        float dx = ((float)(i % 5) - 2.0f - xres) * 0.5f;  // / RADIUS
        float dy = ((float)(i / 5) - 2.0f - yres) * 0.5f;
        dsum += e[i] * (dx * dx + dy * dy);
    }
    float disp = dsum / se;

    float kxy_x = ((float)kx + xres) / 2047.0f * 2.0f - 1.0f;
    float kxy_y = ((float)ky + yres) / 2047.0f * 2.0f - 1.0f;

    // bilinear resample (align_corners=True), matching reference clamp semantics
    float px = (kxy_x + 1.0f) * 0.5f * 2047.0f;
    float py = (kxy_y + 1.0f) * 0.5f * 2047.0f;
    int x0 = min(max((int)floorf(px), 0), W - 1);
    int y0 = min(max((int)floorf(py), 0), H - 1);
    int x1 = min(x0 + 1, W - 1);
    int y1 = min(y0 + 1, H - 1);
    float wx = px - (float)x0;
    float wy = py - (float)y0;
    float v00 = img[y0 * W + x0], v01 = img[y0 * W + x1];
    float v10 = img[y1 * W + x0], v11 = img[y1 * W + x1];
    float ks = v00 * (1.f - wx) * (1.f - wy) + v01 * wx * (1.f - wy)
             + v10 * (1.f - wx) * wy + v11 * wx * wy;

    // output layout: kxy (B,K,2) | kscore (B,K) | disp (B,K)
    out[(size_t)(b * TOPK + k) * 2 + 0] = kxy_x;
    out[(size_t)(b * TOPK + k) * 2 + 1] = kxy_y;
    out[(size_t)BATCH * TOPK * 2 + b * TOPK + k] = ks;
    out[(size_t)BATCH * TOPK * 3 + b * TOPK + k] = disp;
}

// ---------------- launch ----------------
extern "C" void kernel_launch(void* const* d_in, const int* in_sizes, int n_in,
                              void* d_out, int out_size) {
    const float* s = (const float*)d_in[0];
    float* out = (float*)d_out;

    init_a<<<128, 256>>>();
    init_b<<<128, 256>>>();
    init_c<<<1, 32>>>();
    nms_kernel<<<dim3(W / TX, H / TY, BATCH), NTHR>>>(s);       // 4th launch -> ncu capture
    threshold_kernel<<<BATCH, 1024>>>();
    scatter_kernel<<<dim3(96, BATCH), 256>>>();
    sortA_kernel<<<dim3(SA_BLOCKS, BATCH), SA_WPB * 32>>>();
    sortB_kernel<<<BATCH, 256>>>();
    final_kernel<<<(BATCH * TOPK + 255) / 256, 256>>>(s, out);
}